// round 4
// baseline (speedup 1.0000x reference)
#include <cuda_runtime.h>
#include <cstdint>
typedef unsigned long long u64;

#define P 68
#define KH 20
#define WROWS 112

__device__ float g_Ct[16*64*64];   // transposed: [al][fo][fi]
__device__ float g_cb[16*64];
__device__ float g_d[16*64];
__device__ float g_e[16];

__device__ __forceinline__ void fma2(u64& d, u64 a, u64 b){
    asm("fma.rn.f32x2 %0, %1, %2, %0;" : "+l"(d) : "l"(a), "l"(b));
}
__device__ __forceinline__ u64 pk(float a, float b){
    u64 r; asm("mov.b64 %0, {%1, %2};" : "=l"(r) : "f"(a), "f"(b)); return r;
}
__device__ __forceinline__ float hsum(u64 v){
    float x, y; asm("mov.b64 {%0, %1}, %2;" : "=f"(x), "=f"(y) : "l"(v)); return x + y;
}

__global__ __launch_bounds__(256) void precompute_kernel(
    const float* __restrict__ Wq, const float* __restrict__ bq,
    const float* __restrict__ Wk, const float* __restrict__ bk)
{
    __shared__ float sWq[64][65], sWk[64][65], sbq[64], sbk[64];
    int al = blockIdx.x, a = al >> 2, l = al & 3;
    size_t wb = ((size_t)(7 + a) * 5 + l) * 4096;
    size_t bb = ((size_t)(7 + a) * 5 + l) * 64;
    int t = threadIdx.x;
    for (int i = t; i < 4096; i += 256) {
        sWq[i >> 6][i & 63] = Wq[wb + i];
        sWk[i >> 6][i & 63] = Wk[wb + i];
    }
    if (t < 64) { sbq[t] = bq[bb + t]; sbk[t] = bk[bb + t]; }
    __syncthreads();
    int tf = t & 15, ts = t >> 4;
    float acc[4][4] = {};
    for (int g = 0; g < 64; g++) {
        float qv[4], kv[4];
#pragma unroll
        for (int i = 0; i < 4; i++) { qv[i] = sWq[g][ts*4+i]; kv[i] = sWk[g][tf*4+i]; }
#pragma unroll
        for (int i = 0; i < 4; i++)
#pragma unroll
            for (int j = 0; j < 4; j++) acc[i][j] += qv[i] * kv[j];
    }
#pragma unroll
    for (int i = 0; i < 4; i++)   // store transposed [fo][fi]
#pragma unroll
        for (int j = 0; j < 4; j++)
            g_Ct[al*4096 + (tf*4+j)*64 + (ts*4+i)] = acc[i][j];
    if (t < 64) {
        float s = 0.f;
        for (int g = 0; g < 64; g++) s += sbq[g] * sWk[g][t];
        g_cb[al*64 + t] = s;
    } else if (t < 128) {
        int fi = t - 64; float s = 0.f;
        for (int g = 0; g < 64; g++) s += sWq[g][fi] * sbk[g];
        g_d[al*64 + fi] = s;
    } else if (t == 128) {
        float s = 0.f;
        for (int g = 0; g < 64; g++) s += sbq[g] * sbk[g];
        g_e[al] = s;
    }
}

__global__ __launch_bounds__(256, 2) void attn_kernel(
    const float* __restrict__ X, const float* __restrict__ Wt,
    const float* __restrict__ bt, float* __restrict__ out)
{
    extern __shared__ float sm[];
    float* sWin  = sm;                 // WROWS*P, chunk-swizzled
    float* sU    = sWin + WROWS*P;     // 64*P (U, then ctx)
    float* sCt   = sU   + 64*P;        // 64*P  C^T [fo][fi]
    float* sWt   = sCt  + 64*P;        // 64*P  Wt natural [g][f]
    float* sAttn = sWt  + 64*P;        // 64*P
    float* sFlag = sAttn + 64*P;       // 104
    float* sBias = sFlag + 104;        // 64
    float* sBt   = sBias + 64;
    float* scb   = sBt  + 64;
    float* sd    = scb  + 64;

    int bx = blockIdx.x;
    int st = bx & 31, b = (bx >> 5) & 3, al = bx >> 7;
    int a = al >> 2, l = al & 3;
    int s0 = st * 64;
    int t = threadIdx.x;

    for (int q = t; q < WROWS*16; q += 256) {
        int r = q >> 4, c4 = q & 15;
        int sg = s0 - KH + r;
        float4 v = make_float4(0.f, 0.f, 0.f, 0.f);
        if (sg >= 0 && sg < 2048)
            v = *(const float4*)&X[(((size_t)b*2048 + sg)*4 + a)*64 + c4*4];
        int ch = (c4 + (r >> 2)) & 15;
        *(float4*)&sWin[r*P + ch*4] = v;
    }
    for (int q = t; q < 1024; q += 256) {
        int r = q >> 4, c4 = (q & 15) * 4;
        *(float4*)&sCt[r*P + c4] = *(const float4*)&g_Ct[al*4096 + r*64 + c4];
    }
    size_t wb = ((size_t)(7 + a) * 5 + l) * 4096;
    for (int q = t; q < 1024; q += 256) {
        int r = q >> 4, c4 = (q & 15) * 4;
        *(float4*)&sWt[r*P + c4] = *(const float4*)&Wt[wb + r*64 + c4];
    }
    if (t < 64) {
        scb[t] = g_cb[al*64 + t];
        sd[t]  = g_d[al*64 + t];
        sBt[t] = bt[((7 + a)*5 + l)*64 + t];
    }
    __syncthreads();

    if (t < 104) {
        bool nz = false;
        int rq = t >> 2;
        for (int c4 = 0; c4 < 16; c4++) {
            float4 v = *(float4*)&sWin[t*P + ((c4 + rq) & 15)*4];
            nz = nz || v.x != 0.f || v.y != 0.f || v.z != 0.f || v.w != 0.f;
        }
        sFlag[t] = nz ? 1.f : 0.f;
    }

    // ---- U = Xc*C + cb  (NT, k-paired f32x2) ----
    {
        int tf = t & 15, ts = t >> 4, fo0 = tf*4;
        u64 acc[4][4] = {};
#pragma unroll 2
        for (int fi = 0; fi < 64; fi += 4) {
            u64 cA[4], cB[4], xA[4], xB[4];
#pragma unroll
            for (int j = 0; j < 4; j++) {
                cA[j] = *(const u64*)&sCt[(fo0+j)*P + fi];
                cB[j] = *(const u64*)&sCt[(fo0+j)*P + fi + 2];
            }
#pragma unroll
            for (int i = 0; i < 4; i++) {
                int r = KH + ts*4 + i;
                int ch = ((fi >> 2) + (r >> 2)) & 15;
                xA[i] = *(const u64*)&sWin[r*P + ch*4];
                xB[i] = *(const u64*)&sWin[r*P + ch*4 + 2];
            }
#pragma unroll
            for (int i = 0; i < 4; i++)
#pragma unroll
                for (int j = 0; j < 4; j++) {
                    fma2(acc[i][j], xA[i], cA[j]);
                    fma2(acc[i][j], xB[i], cB[j]);
                }
        }
#pragma unroll
        for (int i = 0; i < 4; i++)
#pragma unroll
            for (int j = 0; j < 4; j++)
                sU[(ts*4+i)*P + fo0 + j] = hsum(acc[i][j]) + scb[fo0 + j];
    }
    if (t < 64) {
        int r = KH + t, rq = r >> 2;
        float s = 0.f;
        for (int c = 0; c < 64; c++)
            s += sWin[r*P + (((c >> 2) + rq) & 15)*4 + (c & 3)] * sd[c];
        sBias[t] = s + g_e[al];
    }
    __syncthreads();

    // ---- scores (NT, k-paired) ----
    {
        int sb = t >> 6, tt = t & 63;
        int trr = tt & 15, tss = tt >> 4, R0 = sb * 16;
        u64 acc[4][4] = {};
#pragma unroll 2
        for (int fi = 0; fi < 64; fi += 4) {
            u64 wA[4], wB[4], xA[4], xB[4];
#pragma unroll
            for (int j = 0; j < 4; j++) {
                int r = R0 + trr*4 + j;
                int ch = ((fi >> 2) + (r >> 2)) & 15;
                wA[j] = *(const u64*)&sWin[r*P + ch*4];
                wB[j] = *(const u64*)&sWin[r*P + ch*4 + 2];
            }
#pragma unroll
            for (int i = 0; i < 4; i++) {
                xA[i] = *(const u64*)&sU[(R0 + tss*4 + i)*P + fi];
                xB[i] = *(const u64*)&sU[(R0 + tss*4 + i)*P + fi + 2];
            }
#pragma unroll
            for (int i = 0; i < 4; i++)
#pragma unroll
                for (int j = 0; j < 4; j++) {
                    fma2(acc[i][j], xA[i], wA[j]);
                    fma2(acc[i][j], xB[i], wB[j]);
                }
        }
#pragma unroll
        for (int i = 0; i < 4; i++)
#pragma unroll
            for (int j = 0; j < 4; j++)
                sAttn[(R0 + tss*4 + i)*P + trr*4 + j] = hsum(acc[i][j]);
    }
    __syncthreads();

    if (t < 64) {
        int srem = t & 15;
        float* row = &sAttn[t*P];
        float bias = sBias[t];
        float m = -1e30f;
        for (int j = 0; j <= 40; j++) {
            float v = (row[srem + j] + bias) * 0.125f;
            if (sFlag[t + j] == 0.f) v = -1e9f;
            row[srem + j] = v;
            m = fmaxf(m, v);
        }
        float ssum = 0.f;
        for (int j = 0; j <= 40; j++) {
            float e = __expf(row[srem + j] - m);
            row[srem + j] = e;
            ssum += e;
        }
        float inv = 1.f / ssum;
        for (int rr = 0; rr < 64; rr++)
            row[rr] = (rr >= srem && rr <= srem + 40) ? row[rr] * inv : 0.f;
    }
    __syncthreads();

    // ---- ctx = wgt*win (k-paired over rows, packed b) ----
    {
        int sb = t >> 6, tt = t & 63;
        int tf = tt & 15, tss = tt >> 4, R0 = sb * 16;
        int f0 = tf * 4;
        u64 acc[4][4] = {};
#pragma unroll 2
        for (int rr = 0; rr < 64; rr += 2) {
            int r0 = R0 + rr, r1 = r0 + 1;
            float4 wv0 = *(float4*)&sWin[r0*P + ((tf + (r0 >> 2)) & 15)*4];
            float4 wv1 = *(float4*)&sWin[r1*P + ((tf + (r1 >> 2)) & 15)*4];
            u64 bp[4];
            bp[0] = pk(wv0.x, wv1.x); bp[1] = pk(wv0.y, wv1.y);
            bp[2] = pk(wv0.z, wv1.z); bp[3] = pk(wv0.w, wv1.w);
#pragma unroll
            for (int i = 0; i < 4; i++) {
                u64 ap = *(const u64*)&sAttn[(R0 + tss*4 + i)*P + rr];
#pragma unroll
                for (int j = 0; j < 4; j++) fma2(acc[i][j], ap, bp[j]);
            }
        }
        __syncthreads();
#pragma unroll
        for (int i = 0; i < 4; i++)
#pragma unroll
            for (int j = 0; j < 4; j++)
                sU[(R0 + tss*4 + i)*P + f0 + j] = hsum(acc[i][j]);
    }
    __syncthreads();

    // ---- out = ctx*Wt^T + bt (NT, k-paired) ----
    {
        int tf = t & 15, ts = t >> 4, g0 = tf * 4;
        u64 acc[4][4] = {};
#pragma unroll 2
        for (int f = 0; f < 64; f += 4) {
            u64 wA[4], wB[4], xA[4], xB[4];
#pragma unroll
            for (int j = 0; j < 4; j++) {
                wA[j] = *(const u64*)&sWt[(g0+j)*P + f];
                wB[j] = *(const u64*)&sWt[(g0+j)*P + f + 2];
            }
#pragma unroll
            for (int i = 0; i < 4; i++) {
                xA[i] = *(const u64*)&sU[(ts*4+i)*P + f];
                xB[i] = *(const u64*)&sU[(ts*4+i)*P + f + 2];
            }
#pragma unroll
            for (int i = 0; i < 4; i++)
#pragma unroll
                for (int j = 0; j < 4; j++) {
                    fma2(acc[i][j], xA[i], wA[j]);
                    fma2(acc[i][j], xB[i], wB[j]);
                }
        }
#pragma unroll
        for (int i = 0; i < 4; i++) {
            int q = ts*4 + i;
            size_t idx = ((((size_t)b*2048 + s0 + q)*4 + a)*4 + l)*64 + g0;
            float4 o = make_float4(hsum(acc[i][0]) + sBt[g0],   hsum(acc[i][1]) + sBt[g0+1],
                                   hsum(acc[i][2]) + sBt[g0+2], hsum(acc[i][3]) + sBt[g0+3]);
            *(float4*)&out[idx] = o;
        }
    }
}

#define SMEM_BYTES ((WROWS*P + 4*64*P + 104 + 4*64) * 4)

extern "C" void kernel_launch(void* const* d_in, const int* in_sizes, int n_in,
                              void* d_out, int out_size) {
    (void)in_sizes; (void)n_in; (void)out_size;
    const float* X  = (const float*)d_in[0];
    const float* Wq = (const float*)d_in[1];
    const float* bq = (const float*)d_in[2];
    const float* Wk = (const float*)d_in[3];
    const float* bk = (const float*)d_in[4];
    const float* Wt = (const float*)d_in[5];
    const float* bt = (const float*)d_in[6];
    float* out = (float*)d_out;
    cudaFuncSetAttribute(attn_kernel, cudaFuncAttributeMaxDynamicSharedMemorySize, SMEM_BYTES);
    precompute_kernel<<<16, 256>>>(Wq, bq, Wk, bk);
    attn_kernel<<<2048, 256, SMEM_BYTES>>>(X, Wt, bt, out);
}

// round 5
// speedup vs baseline: 1.9501x; 1.9501x over previous
#include <cuda_runtime.h>
#include <cstdint>

#define P 68
#define KH 20
#define WROWS 112

__device__ float g_Ct[16*64*64];   // [al][fo][fi]
__device__ float g_cb[16*64];
__device__ float g_d[16*64];
__device__ float g_e[16];

// ---- tf32 helpers ----
__device__ __forceinline__ void spl(float x, uint32_t& h, uint32_t& l){
    asm("cvt.rna.tf32.f32 %0, %1;" : "=r"(h) : "f"(x));
    float hf = __uint_as_float(h);
    asm("cvt.rna.tf32.f32 %0, %1;" : "=r"(l) : "f"(x - hf));
}
#define MMA(d, a, b) asm volatile( \
  "mma.sync.aligned.m16n8k8.row.col.f32.tf32.tf32.f32 " \
  "{%0,%1,%2,%3},{%4,%5,%6,%7},{%8,%9},{%0,%1,%2,%3};" \
  : "+f"((d)[0]),"+f"((d)[1]),"+f"((d)[2]),"+f"((d)[3]) \
  : "r"((a)[0]),"r"((a)[1]),"r"((a)[2]),"r"((a)[3]),"r"((b)[0]),"r"((b)[1]))

__device__ __forceinline__ void mma3(float* d, const uint32_t* ah, const uint32_t* al,
                                     const uint32_t* bh, const uint32_t* bl){
    MMA(d, ah, bh); MMA(d, al, bh); MMA(d, ah, bl);
}
// A fragment: row-major M[r][k], rows r0+gid(+8), cols k0+tig(+4)
__device__ __forceinline__ void ldA(const float* M, int r0, int k0, int gid, int tig,
                                    uint32_t* ah, uint32_t* al){
    float v0 = M[(r0+gid)*P + k0+tig];
    float v1 = M[(r0+gid+8)*P + k0+tig];
    float v2 = M[(r0+gid)*P + k0+tig+4];
    float v3 = M[(r0+gid+8)*P + k0+tig+4];
    spl(v0, ah[0], al[0]); spl(v1, ah[1], al[1]);
    spl(v2, ah[2], al[2]); spl(v3, ah[3], al[3]);
}
// B fragment from NT storage arr[n][k]: B[k][n] = arr[n*P+k]
__device__ __forceinline__ void ldBnt(const float* M, int n0, int k0, int gid, int tig,
                                      uint32_t* bh, uint32_t* bl){
    float v0 = M[(n0+gid)*P + k0+tig];
    float v1 = M[(n0+gid)*P + k0+tig+4];
    spl(v0, bh[0], bl[0]); spl(v1, bh[1], bl[1]);
}
// B fragment from T storage arr[k][n]
__device__ __forceinline__ void ldBt(const float* M, int n0, int k0, int gid, int tig,
                                     uint32_t* bh, uint32_t* bl){
    float v0 = M[(k0+tig)*P + n0+gid];
    float v1 = M[(k0+tig+4)*P + n0+gid];
    spl(v0, bh[0], bl[0]); spl(v1, bh[1], bl[1]);
}

__global__ __launch_bounds__(256) void precompute_kernel(
    const float* __restrict__ Wq, const float* __restrict__ bq,
    const float* __restrict__ Wk, const float* __restrict__ bk)
{
    __shared__ float sWq[64][65], sWk[64][65], sbq[64], sbk[64];
    int al = blockIdx.x, a = al >> 2, l = al & 3;
    size_t wb = ((size_t)(7 + a) * 5 + l) * 4096;
    size_t bb = ((size_t)(7 + a) * 5 + l) * 64;
    int t = threadIdx.x;
    for (int i = t; i < 4096; i += 256) {
        sWq[i >> 6][i & 63] = Wq[wb + i];
        sWk[i >> 6][i & 63] = Wk[wb + i];
    }
    if (t < 64) { sbq[t] = bq[bb + t]; sbk[t] = bk[bb + t]; }
    __syncthreads();
    int tf = t & 15, ts = t >> 4;
    float acc[4][4] = {};
    for (int g = 0; g < 64; g++) {
        float qv[4], kv[4];
#pragma unroll
        for (int i = 0; i < 4; i++) { qv[i] = sWq[g][ts*4+i]; kv[i] = sWk[g][tf*4+i]; }
#pragma unroll
        for (int i = 0; i < 4; i++)
#pragma unroll
            for (int j = 0; j < 4; j++) acc[i][j] += qv[i] * kv[j];
    }
#pragma unroll
    for (int i = 0; i < 4; i++)
#pragma unroll
        for (int j = 0; j < 4; j++)
            g_Ct[al*4096 + (tf*4+j)*64 + (ts*4+i)] = acc[i][j];
    if (t < 64) {
        float s = 0.f;
        for (int g = 0; g < 64; g++) s += sbq[g] * sWk[g][t];
        g_cb[al*64 + t] = s;
    } else if (t < 128) {
        int fi = t - 64; float s = 0.f;
        for (int g = 0; g < 64; g++) s += sWq[g][fi] * sbk[g];
        g_d[al*64 + fi] = s;
    } else if (t == 128) {
        float s = 0.f;
        for (int g = 0; g < 64; g++) s += sbq[g] * sbk[g];
        g_e[al] = s;
    }
}

__global__ __launch_bounds__(256, 2) void attn_kernel(
    const float* __restrict__ X, const float* __restrict__ Wt,
    const float* __restrict__ bt, float* __restrict__ out)
{
    extern __shared__ float sm[];
    float* sWin  = sm;                 // [112][P] row-major, NO swizzle
    float* sU    = sWin + WROWS*P;     // [64][P]   U, then ctx
    float* sCt   = sU   + 64*P;        // [64][P]   C^T [fo][fi]
    float* sWt   = sCt  + 64*P;        // [64][P]   Wt [g][f]
    float* sAttn = sWt  + 64*P;        // [64][P]   banded scores [q][rel]
    float* sFlag = sAttn + 64*P;       // 104
    float* sBias = sFlag + 104;        // 64
    float* sBt   = sBias + 64;
    float* scb   = sBt  + 64;
    float* sd    = scb  + 64;

    int bx = blockIdx.x;
    int st = bx & 31, b = (bx >> 5) & 3, al = bx >> 7;
    int a = al >> 2, l = al & 3;
    int s0 = st * 64;
    int t = threadIdx.x;
    int w = t >> 5, lane = t & 31;
    int gid = lane >> 2, tig = lane & 3;
    int mb = w & 3, h = w >> 2;        // m-block 0..3, n-half 0..1
    int m0 = mb * 16;

    for (int q = t; q < WROWS*16; q += 256) {
        int r = q >> 4, c4 = q & 15;
        int sg = s0 - KH + r;
        float4 v = make_float4(0.f, 0.f, 0.f, 0.f);
        if (sg >= 0 && sg < 2048)
            v = *(const float4*)&X[(((size_t)b*2048 + sg)*4 + a)*64 + c4*4];
        *(float4*)&sWin[r*P + c4*4] = v;
    }
    for (int q = t; q < 1024; q += 256) {
        int r = q >> 4, c4 = (q & 15) * 4;
        *(float4*)&sCt[r*P + c4] = *(const float4*)&g_Ct[al*4096 + r*64 + c4];
    }
    size_t wb = ((size_t)(7 + a) * 5 + l) * 4096;
    for (int q = t; q < 1024; q += 256) {
        int r = q >> 4, c4 = (q & 15) * 4;
        *(float4*)&sWt[r*P + c4] = *(const float4*)&Wt[wb + r*64 + c4];
    }
    if (t < 64) {
        scb[t] = g_cb[al*64 + t];
        sd[t]  = g_d[al*64 + t];
        sBt[t] = bt[((7 + a)*5 + l)*64 + t];
    }
    __syncthreads();

    if (t < 104) {
        bool nz = false;
        for (int c4 = 0; c4 < 16; c4++) {
            float4 v = *(float4*)&sWin[t*P + c4*4];
            nz = nz || v.x != 0.f || v.y != 0.f || v.z != 0.f || v.w != 0.f;
        }
        sFlag[t] = nz ? 1.f : 0.f;
    }

    // ---- U = Xc*C + cb : warp does 16q x 32fo (4 n-tiles), K=64 ----
    {
        float d[4][4] = {};
        uint32_t ah[4], alo[4], bh[2], bl[2];
#pragma unroll
        for (int ks = 0; ks < 8; ks++) {
            int k0 = ks * 8;
            ldA(sWin, KH + m0, k0, gid, tig, ah, alo);
#pragma unroll
            for (int nt = 0; nt < 4; nt++) {
                ldBnt(sCt, h*32 + nt*8, k0, gid, tig, bh, bl);
                mma3(d[nt], ah, alo, bh, bl);
            }
        }
#pragma unroll
        for (int nt = 0; nt < 4; nt++) {
            int c0 = h*32 + nt*8 + 2*tig;
            sU[(m0+gid)*P + c0]     = d[nt][0] + scb[c0];
            sU[(m0+gid)*P + c0+1]   = d[nt][1] + scb[c0+1];
            sU[(m0+gid+8)*P + c0]   = d[nt][2] + scb[c0];
            sU[(m0+gid+8)*P + c0+1] = d[nt][3] + scb[c0+1];
        }
    }
    if (t < 64) {
        int r = KH + t;
        float s = 0.f;
        for (int c = 0; c < 64; c++) s += sWin[r*P + c] * sd[c];
        sBias[t] = s + g_e[al];
    }
    __syncthreads();

    // ---- scores: q-block mb vs window rows [m0, m0+56), banded. h=0: rel 0..31, h=1: rel 32..55 ----
    {
        int ntiles = (h == 0) ? 4 : 3;
        float d[4][4] = {};
        uint32_t ah[4], alo[4], bh[2], bl[2];
#pragma unroll
        for (int ks = 0; ks < 8; ks++) {
            int k0 = ks * 8;
            ldA(sU, m0, k0, gid, tig, ah, alo);
            for (int nt = 0; nt < ntiles; nt++) {
                int rel0 = h*32 + nt*8;
                ldBnt(sWin, m0 + rel0, k0, gid, tig, bh, bl);
                mma3(d[nt], ah, alo, bh, bl);
            }
        }
        for (int nt = 0; nt < ntiles; nt++) {
            int c0 = h*32 + nt*8 + 2*tig;
            sAttn[(m0+gid)*P + c0]     = d[nt][0];
            sAttn[(m0+gid)*P + c0+1]   = d[nt][1];
            sAttn[(m0+gid+8)*P + c0]   = d[nt][2];
            sAttn[(m0+gid+8)*P + c0+1] = d[nt][3];
        }
    }
    __syncthreads();

    // ---- softmax (sAttn[q][rel], band at rel = (q&15)+j, j in [0,40]) ----
    if (t < 64) {
        int srem = t & 15;
        float* row = &sAttn[t*P];
        float bias = sBias[t];
        float m = -1e30f;
        for (int j = 0; j <= 40; j++) {
            float v = (row[srem + j] + bias) * 0.125f;
            if (sFlag[t + j] == 0.f) v = -1e9f;
            row[srem + j] = v;
            m = fmaxf(m, v);
        }
        float ssum = 0.f;
        for (int j = 0; j <= 40; j++) {
            float e = __expf(row[srem + j] - m);
            row[srem + j] = e;
            ssum += e;
        }
        float inv = 1.f / ssum;
        for (int rr = 0; rr < 56; rr++)
            row[rr] = (rr >= srem && rr <= srem + 40) ? row[rr] * inv : 0.f;
    }
    __syncthreads();

    // ---- ctx = wgt*win : A=sAttn[q][rel] K=56, B=sWin[m0+rel][f] (T layout), N=64 ----
    {
        float d[4][4] = {};
        uint32_t ah[4], alo[4], bh[2], bl[2];
#pragma unroll
        for (int ks = 0; ks < 7; ks++) {
            int k0 = ks * 8;
            ldA(sAttn, m0, k0, gid, tig, ah, alo);
#pragma unroll
            for (int nt = 0; nt < 4; nt++) {
                ldBt(sWin, h*32 + nt*8, m0 + k0, gid, tig, bh, bl);
                mma3(d[nt], ah, alo, bh, bl);
            }
        }
        __syncthreads();   // sU (U) fully consumed by scores; safe to overwrite
#pragma unroll
        for (int nt = 0; nt < 4; nt++) {
            int c0 = h*32 + nt*8 + 2*tig;
            sU[(m0+gid)*P + c0]     = d[nt][0];
            sU[(m0+gid)*P + c0+1]   = d[nt][1];
            sU[(m0+gid+8)*P + c0]   = d[nt][2];
            sU[(m0+gid+8)*P + c0+1] = d[nt][3];
        }
    }
    __syncthreads();

    // ---- out = ctx*Wt^T + bt ----
    {
        float d[4][4] = {};
        uint32_t ah[4], alo[4], bh[2], bl[2];
#pragma unroll
        for (int ks = 0; ks < 8; ks++) {
            int k0 = ks * 8;
            ldA(sU, m0, k0, gid, tig, ah, alo);
#pragma unroll
            for (int nt = 0; nt < 4; nt++) {
                ldBnt(sWt, h*32 + nt*8, k0, gid, tig, bh, bl);
                mma3(d[nt], ah, alo, bh, bl);
            }
        }
#pragma unroll
        for (int nt = 0; nt < 4; nt++) {
            int c0 = h*32 + nt*8 + 2*tig;
            int q0 = m0 + gid, q1 = m0 + gid + 8;
            size_t i0 = ((((size_t)b*2048 + s0 + q0)*4 + a)*4 + l)*64 + c0;
            size_t i1 = ((((size_t)b*2048 + s0 + q1)*4 + a)*4 + l)*64 + c0;
            float2 o0 = make_float2(d[nt][0] + sBt[c0], d[nt][1] + sBt[c0+1]);
            float2 o1 = make_float2(d[nt][2] + sBt[c0], d[nt][3] + sBt[c0+1]);
            *(float2*)&out[i0] = o0;
            *(float2*)&out[i1] = o1;
        }
    }
}

#define SMEM_BYTES ((WROWS*P + 4*64*P + 104 + 4*64) * 4)

extern "C" void kernel_launch(void* const* d_in, const int* in_sizes, int n_in,
                              void* d_out, int out_size) {
    (void)in_sizes; (void)n_in; (void)out_size;
    const float* X  = (const float*)d_in[0];
    const float* Wq = (const float*)d_in[1];
    const float* bq = (const float*)d_in[2];
    const float* Wk = (const float*)d_in[3];
    const float* bk = (const float*)d_in[4];
    const float* Wt = (const float*)d_in[5];
    const float* bt = (const float*)d_in[6];
    float* out = (float*)d_out;
    cudaFuncSetAttribute(attn_kernel, cudaFuncAttributeMaxDynamicSharedMemorySize, SMEM_BYTES);
    precompute_kernel<<<16, 256>>>(Wq, bq, Wk, bk);
    attn_kernel<<<2048, 256, SMEM_BYTES>>>(X, Wt, bt, out);
}

// round 8
// speedup vs baseline: 2.3183x; 1.1888x over previous
#include <cuda_runtime.h>
#include <cuda_bf16.h>
#include <cstdint>
typedef unsigned short u16;
typedef uint32_t u32;

#define KH 20
#define PW 36          // plane pitch in u32 (72 bf16)
#define PA 68          // f32 attn pitch

__device__ u16 g_CtH[16*4096], g_CtL[16*4096];   // [al][fo][fi]
__device__ u16 g_WtH[16*4096], g_WtL[16*4096];   // [al][g][f]
__device__ float g_cb[16*64];

__device__ __forceinline__ u32 bf2(float a, float b){  // pack a->lo16, b->hi16
    u32 r; asm("cvt.rn.bf16x2.f32 %0, %1, %2;" : "=r"(r) : "f"(b), "f"(a)); return r;
}
__device__ __forceinline__ void splitp(float a, float b, u32& hi, u32& lo){
    hi = bf2(a, b);
    float ha = __uint_as_float(hi << 16);
    float hb = __uint_as_float(hi & 0xFFFF0000u);
    lo = bf2(a - ha, b - hb);
}
__device__ __forceinline__ void splits(float v, u16& hs, u16& ls){
    u32 hi, lo;
    splitp(v, 0.f, hi, lo);
    hs = (u16)(hi & 0xFFFFu);
    ls = (u16)(lo & 0xFFFFu);
}
#define MMAB(d, a, b) asm volatile( \
  "mma.sync.aligned.m16n8k16.row.col.f32.bf16.bf16.f32 " \
  "{%0,%1,%2,%3},{%4,%5,%6,%7},{%8,%9},{%0,%1,%2,%3};" \
  : "+f"((d)[0]),"+f"((d)[1]),"+f"((d)[2]),"+f"((d)[3]) \
  : "r"((a)[0]),"r"((a)[1]),"r"((a)[2]),"r"((a)[3]),"r"((b)[0]),"r"((b)[1]))
__device__ __forceinline__ void mma3(float* d, const u32* ah, const u32* al,
                                     const u32* bh, const u32* bl){
    MMAB(d, ah, bh); MMAB(d, al, bh); MMAB(d, ah, bl);
}
__device__ __forceinline__ void ldA(const u32* H, const u32* L, int r0, int k0s,
                                    int gid, int tig, u32* ah, u32* al){
    int i0 = (r0+gid)*PW + k0s + tig;
    ah[0] = H[i0];        ah[1] = H[i0 + 8*PW];
    ah[2] = H[i0 + 4];    ah[3] = H[i0 + 8*PW + 4];
    al[0] = L[i0];        al[1] = L[i0 + 8*PW];
    al[2] = L[i0 + 4];    al[3] = L[i0 + 8*PW + 4];
}
__device__ __forceinline__ void ldB(const u32* H, const u32* L, int n0, int k0s,
                                    int gid, int tig, u32* bh, u32* bl){
    int i0 = (n0+gid)*PW + k0s + tig;
    bh[0] = H[i0]; bh[1] = H[i0 + 4];
    bl[0] = L[i0]; bl[1] = L[i0 + 4];
}

__global__ __launch_bounds__(256) void precompute_kernel(
    const float* __restrict__ Wq, const float* __restrict__ bq,
    const float* __restrict__ Wk, const float* __restrict__ Wt)
{
    __shared__ float sWq[64][65], sWk[64][65], sbq[64];
    int al = blockIdx.x, a = al >> 2, l = al & 3;
    size_t wb = ((size_t)(7 + a) * 5 + l) * 4096;
    size_t bb = ((size_t)(7 + a) * 5 + l) * 64;
    int t = threadIdx.x;
    for (int i = t; i < 4096; i += 256) {
        sWq[i >> 6][i & 63] = Wq[wb + i];
        sWk[i >> 6][i & 63] = Wk[wb + i];
        u16 hs, ls;
        splits(Wt[wb + i], hs, ls);
        g_WtH[al*4096 + i] = hs; g_WtL[al*4096 + i] = ls;
    }
    if (t < 64) sbq[t] = bq[bb + t];
    __syncthreads();
    int tf = t & 15, ts = t >> 4;
    float acc[4][4] = {};
    for (int g = 0; g < 64; g++) {
        float qv[4], kv[4];
#pragma unroll
        for (int i = 0; i < 4; i++) { qv[i] = sWq[g][ts*4+i]; kv[i] = sWk[g][tf*4+i]; }
#pragma unroll
        for (int i = 0; i < 4; i++)
#pragma unroll
            for (int j = 0; j < 4; j++) acc[i][j] += qv[i] * kv[j];
    }
#pragma unroll
    for (int i = 0; i < 4; i++)
#pragma unroll
        for (int j = 0; j < 4; j++) {
            u16 hs, ls;
            splits(acc[i][j], hs, ls);
            int idx = al*4096 + (tf*4+j)*64 + (ts*4+i);
            g_CtH[idx] = hs; g_CtL[idx] = ls;
        }
    if (t < 64) {
        float s = 0.f;
        for (int g = 0; g < 64; g++) s += sbq[g] * sWk[g][t];
        g_cb[al*64 + t] = s;
    }
}

__global__ __launch_bounds__(256, 2) void attn_kernel(
    const float* __restrict__ X, const float* __restrict__ bt,
    float* __restrict__ out)
{
    extern __shared__ u32 sm[];
    u32* winH = sm;                    // [112][PW]
    u32* winL = winH + 112*PW;
    u32* ctH  = winL + 112*PW;         // [64][PW] C^T, reused as wgtH
    u32* ctL  = ctH + 64*PW;
    u32* wtH  = ctL + 64*PW;
    u32* wtL  = wtH + 64*PW;
    u32* uH   = wtL + 64*PW;           // U planes, reused as ctx
    u32* uL   = uH + 64*PW;
    float* sAttn = (float*)(uL + 64*PW);   // [64][PA]
    float* sFlag = sAttn + 64*PA;          // 112
    float* sBt   = sFlag + 112;            // 64
    float* scb   = sBt + 64;               // 64

    int bx = blockIdx.x;
    int st = bx & 31, b = (bx >> 5) & 3, al = bx >> 7;
    int a = al >> 2, l = al & 3;
    int s0 = st * 64;
    int t = threadIdx.x;
    int lane = t & 31;
    int gid = lane >> 2, tig = lane & 3;
    int w = t >> 5, mb = w & 3, h = w >> 2;
    int m0 = mb * 16;

    // ---- window load: split to planes + ballot flags ----
#pragma unroll
    for (int it = 0; it < 7; it++) {
        int q = t + it*256;
        int r = q >> 4, c4 = q & 15;
        int sg = s0 - KH + r;
        float4 v = make_float4(0.f, 0.f, 0.f, 0.f);
        if (sg >= 0 && sg < 2048)
            v = *(const float4*)&X[(((size_t)b*2048 + sg)*4 + a)*64 + c4*4];
        u32 h01, l01, h23, l23;
        splitp(v.x, v.y, h01, l01);
        splitp(v.z, v.w, h23, l23);
        winH[r*PW + c4*2] = h01; winH[r*PW + c4*2 + 1] = h23;
        winL[r*PW + c4*2] = l01; winL[r*PW + c4*2 + 1] = l23;
        bool nz = (v.x != 0.f) | (v.y != 0.f) | (v.z != 0.f) | (v.w != 0.f);
        u32 m = __ballot_sync(0xFFFFFFFFu, nz);
        if (lane == 0)  sFlag[r]     = (m & 0xFFFFu) ? 1.f : 0.f;
        if (lane == 16) sFlag[r]     = (m >> 16)     ? 1.f : 0.f;
    }
    // ---- C^T / Wt planes from global (already split): 2048 u32 each ----
    const u32* gCtH = (const u32*)g_CtH + al*2048;
    const u32* gCtL = (const u32*)g_CtL + al*2048;
    const u32* gWtH = (const u32*)g_WtH + al*2048;
    const u32* gWtL = (const u32*)g_WtL + al*2048;
#pragma unroll
    for (int it = 0; it < 8; it++) {
        int q = t + it*256;
        int r = q >> 5, c = q & 31;
        ctH[r*PW + c] = gCtH[q]; ctL[r*PW + c] = gCtL[q];
        wtH[r*PW + c] = gWtH[q]; wtL[r*PW + c] = gWtL[q];
    }
    if (t < 64) {
        scb[t] = g_cb[al*64 + t];
        sBt[t] = bt[((7 + a)*5 + l)*64 + t];
    }
    __syncthreads();

    // ---- U = Xc*C + cb ----
    {
        float d[4][4] = {};
        u32 ah[4], alo[4], bh[2], bl[2];
#pragma unroll
        for (int ks = 0; ks < 4; ks++) {
            int k0s = ks * 8;
            ldA(winH, winL, KH + m0, k0s, gid, tig, ah, alo);
#pragma unroll
            for (int nt = 0; nt < 4; nt++) {
                ldB(ctH, ctL, h*32 + nt*8, k0s, gid, tig, bh, bl);
                mma3(d[nt], ah, alo, bh, bl);
            }
        }
#pragma unroll
        for (int nt = 0; nt < 4; nt++) {
            int c0 = h*32 + nt*8 + tig*2;
            float cb0 = scb[c0], cb1 = scb[c0+1];
            u32 hi, lo;
            splitp(d[nt][0] + cb0, d[nt][1] + cb1, hi, lo);
            uH[(m0+gid)*PW + c0/2] = hi; uL[(m0+gid)*PW + c0/2] = lo;
            splitp(d[nt][2] + cb0, d[nt][3] + cb1, hi, lo);
            uH[(m0+gid+8)*PW + c0/2] = hi; uL[(m0+gid+8)*PW + c0/2] = lo;
        }
    }
    __syncthreads();

    // ---- scores: U (A) x win rows m0+rel (B), K=64 ----
    {
        int ntiles = (h == 0) ? 4 : 3;
        float d[4][4] = {};
        u32 ah[4], alo[4], bh[2], bl[2];
#pragma unroll
        for (int ks = 0; ks < 4; ks++) {
            int k0s = ks * 8;
            ldA(uH, uL, m0, k0s, gid, tig, ah, alo);
            for (int nt = 0; nt < ntiles; nt++) {
                ldB(winH, winL, m0 + h*32 + nt*8, k0s, gid, tig, bh, bl);
                mma3(d[nt], ah, alo, bh, bl);
            }
        }
        for (int nt = 0; nt < ntiles; nt++) {
            int c0 = h*32 + nt*8 + tig*2;
            sAttn[(m0+gid)*PA + c0]     = d[nt][0];
            sAttn[(m0+gid)*PA + c0+1]   = d[nt][1];
            sAttn[(m0+gid+8)*PA + c0]   = d[nt][2];
            sAttn[(m0+gid+8)*PA + c0+1] = d[nt][3];
        }
    }
    __syncthreads();

    // ---- softmax + write wgt planes (reuse ct planes) ----
    if (t < 64) {
        int srem = t & 15;
        float* row = &sAttn[t*PA];
        float m = -1e30f;
        for (int j = 0; j <= 40; j++) {
            float v = row[srem + j] * 0.125f;
            if (sFlag[t + j] == 0.f) v = -1e9f;
            row[srem + j] = v;
            m = fmaxf(m, v);
        }
        float ssum = 0.f;
        for (int j = 0; j <= 40; j++) {
            float e = __expf(row[srem + j] - m);
            row[srem + j] = e;
            ssum += e;
        }
        float inv = 1.f / ssum;
        for (int rr = 0; rr < 64; rr += 2) {
            float w0 = (rr   >= srem && rr   <= srem + 40) ? row[rr]   * inv : 0.f;
            float w1 = (rr+1 >= srem && rr+1 <= srem + 40) ? row[rr+1] * inv : 0.f;
            u32 hi, lo;
            splitp(w0, w1, hi, lo);
            ctH[t*PW + rr/2] = hi; ctL[t*PW + rr/2] = lo;
        }
    }
    __syncthreads();

    // ---- ctx = wgt x win (B packed on the fly from column pairs) ----
    {
        const u16* whu = (const u16*)winH;
        const u16* wlu = (const u16*)winL;
        float d[4][4] = {};
        u32 ah[4], alo[4], bh[2], bl[2];
#pragma unroll
        for (int ks = 0; ks < 4; ks++) {
            int k0s = ks * 8;
            ldA(ctH, ctL, m0, k0s, gid, tig, ah, alo);
#pragma unroll
            for (int nt = 0; nt < 4; nt++) {
                int n = h*32 + nt*8 + gid;
                int r0 = (m0 + ks*16 + tig*2) * (PW*2) + n;
                bh[0] = (u32)whu[r0]        | ((u32)whu[r0 + PW*2] << 16);
                bh[1] = (u32)whu[r0+16*PW]  | ((u32)whu[r0 + 18*PW] << 16);
                bl[0] = (u32)wlu[r0]        | ((u32)wlu[r0 + PW*2] << 16);
                bl[1] = (u32)wlu[r0+16*PW]  | ((u32)wlu[r0 + 18*PW] << 16);
                mma3(d[nt], ah, alo, bh, bl);
            }
        }
        __syncthreads();   // U planes fully consumed by scores; safe to overwrite
#pragma unroll
        for (int nt = 0; nt < 4; nt++) {
            int c0 = h*32 + nt*8 + tig*2;
            u32 hi, lo;
            splitp(d[nt][0], d[nt][1], hi, lo);
            uH[(m0+gid)*PW + c0/2] = hi; uL[(m0+gid)*PW + c0/2] = lo;
            splitp(d[nt][2], d[nt][3], hi, lo);
            uH[(m0+gid+8)*PW + c0/2] = hi; uL[(m0+gid+8)*PW + c0/2] = lo;
        }
    }
    __syncthreads();

    // ---- out = ctx x Wt^T + bt ----
    {
        float d[4][4] = {};
        u32 ah[4], alo[4], bh[2], bl[2];
#pragma unroll
        for (int ks = 0; ks < 4; ks++) {
            int k0s = ks * 8;
            ldA(uH, uL, m0, k0s, gid, tig, ah, alo);
#pragma unroll
            for (int nt = 0; nt < 4; nt++) {
                ldB(wtH, wtL, h*32 + nt*8, k0s, gid, tig, bh, bl);
                mma3(d[nt], ah, alo, bh, bl);
            }
        }
#pragma unroll
        for (int nt = 0; nt < 4; nt++) {
            int c0 = h*32 + nt*8 + tig*2;
            int q0 = m0 + gid, q1 = m0 + gid + 8;
            size_t i0 = ((((size_t)b*2048 + s0 + q0)*4 + a)*4 + l)*64 + c0;
            size_t i1 = ((((size_t)b*2048 + s0 + q1)*4 + a)*4 + l)*64 + c0;
            *(float2*)&out[i0] = make_float2(d[nt][0] + sBt[c0], d[nt][1] + sBt[c0+1]);
            *(float2*)&out[i1] = make_float2(d[nt][2] + sBt[c0], d[nt][3] + sBt[c0+1]);
        }
    }
}

#define SMEM_BYTES ((112*PW*2 + 64*PW*6 + 64*PA + 112 + 128) * 4)

extern "C" void kernel_launch(void* const* d_in, const int* in_sizes, int n_in,
                              void* d_out, int out_size) {
    (void)in_sizes; (void)n_in; (void)out_size;
    const float* X  = (const float*)d_in[0];
    const float* Wq = (const float*)d_in[1];
    const float* bq = (const float*)d_in[2];
    const float* Wk = (const float*)d_in[3];
    const float* Wt = (const float*)d_in[5];
    const float* bt = (const float*)d_in[6];
    float* out = (float*)d_out;
    cudaFuncSetAttribute(attn_kernel, cudaFuncAttributeMaxDynamicSharedMemorySize, SMEM_BYTES);
    precompute_kernel<<<16, 256>>>(Wq, bq, Wk, Wt);
    attn_kernel<<<2048, 256, SMEM_BYTES>>>(X, bt, out);
}

// round 9
// speedup vs baseline: 2.7097x; 1.1688x over previous
#include <cuda_runtime.h>
#include <cuda_bf16.h>
#include <cstdint>
typedef unsigned short u16;
typedef uint32_t u32;

#define KH 20
#define PW 36            // plane pitch in u32
#define PWB 144          // plane pitch in bytes
#define PA 68            // f32 attn pitch

__device__ u16 g_CtH[16*4096], g_CtL[16*4096];   // [al][fo][fi]
__device__ u16 g_WtH[16*4096], g_WtL[16*4096];   // [al][g][f]
__device__ float g_cb[16*64];

__device__ __forceinline__ u32 bf2(float a, float b){
    u32 r; asm("cvt.rn.bf16x2.f32 %0, %1, %2;" : "=r"(r) : "f"(b), "f"(a)); return r;
}
__device__ __forceinline__ void splitp(float a, float b, u32& hi, u32& lo){
    hi = bf2(a, b);
    float ha = __uint_as_float(hi << 16);
    float hb = __uint_as_float(hi & 0xFFFF0000u);
    lo = bf2(a - ha, b - hb);
}
__device__ __forceinline__ void splits(float v, u16& hs, u16& ls){
    u32 hi, lo;
    splitp(v, 0.f, hi, lo);
    hs = (u16)(hi & 0xFFFFu); ls = (u16)(lo & 0xFFFFu);
}
__device__ __forceinline__ u32 s2u(const void* p){
    u32 a; asm("{ .reg .u64 t; cvta.to.shared.u64 t, %1; cvt.u32.u64 %0, t; }" : "=r"(a) : "l"(p));
    return a;
}
#define MMAB(d, a, b) asm volatile( \
  "mma.sync.aligned.m16n8k16.row.col.f32.bf16.bf16.f32 " \
  "{%0,%1,%2,%3},{%4,%5,%6,%7},{%8,%9},{%0,%1,%2,%3};" \
  : "+f"((d)[0]),"+f"((d)[1]),"+f"((d)[2]),"+f"((d)[3]) \
  : "r"((a)[0]),"r"((a)[1]),"r"((a)[2]),"r"((a)[3]),"r"((b)[0]),"r"((b)[1]))
__device__ __forceinline__ void mma3(float* d, const u32* ah, const u32* al,
                                     const u32* bh, const u32* bl){
    MMAB(d, ah, bh); MMAB(d, al, bh); MMAB(d, ah, bl);
}
#define LDSM4(r, ad) asm volatile("ldmatrix.sync.aligned.m8n8.x4.shared.b16 {%0,%1,%2,%3}, [%4];" \
    : "=r"((r)[0]),"=r"((r)[1]),"=r"((r)[2]),"=r"((r)[3]) : "r"(ad))
#define LDSM2(r, ad) asm volatile("ldmatrix.sync.aligned.m8n8.x2.shared.b16 {%0,%1}, [%2];" \
    : "=r"((r)[0]),"=r"((r)[1]) : "r"(ad))
#define LDSM2T(r, ad) asm volatile("ldmatrix.sync.aligned.m8n8.x2.trans.shared.b16 {%0,%1}, [%2];" \
    : "=r"((r)[0]),"=r"((r)[1]) : "r"(ad))

// ---------------- precompute: grid (16, 4) ----------------
__global__ __launch_bounds__(256) void precompute_kernel(
    const float* __restrict__ Wq, const float* __restrict__ bq,
    const float* __restrict__ Wk, const float* __restrict__ Wt)
{
    __shared__ float sWq[64][65], sWk[64][65], sbq[64];
    int al = blockIdx.x, y = blockIdx.y;
    int a = al >> 2, l = al & 3;
    size_t wb = ((size_t)(7 + a) * 5 + l) * 4096;
    size_t bb = ((size_t)(7 + a) * 5 + l) * 64;
    int t = threadIdx.x;
    for (int i = t; i < 4096; i += 256) {
        sWq[i >> 6][i & 63] = Wq[wb + i];
        sWk[i >> 6][i & 63] = Wk[wb + i];
    }
#pragma unroll
    for (int it = 0; it < 4; it++) {
        int i = y*1024 + it*256 + t;
        u16 hs, ls;
        splits(Wt[wb + i], hs, ls);
        g_WtH[al*4096 + i] = hs; g_WtL[al*4096 + i] = ls;
    }
    if (t < 64) sbq[t] = bq[bb + t];
    __syncthreads();
    int tf = t & 15, fr = t >> 4;
    int fi = y*16 + fr;
    float acc[4] = {};
    for (int g = 0; g < 64; g++) {
        float qv = sWq[g][fi];
#pragma unroll
        for (int j = 0; j < 4; j++) acc[j] += qv * sWk[g][tf*4 + j];
    }
#pragma unroll
    for (int j = 0; j < 4; j++) {
        u16 hs, ls;
        splits(acc[j], hs, ls);
        int idx = al*4096 + (tf*4+j)*64 + fi;
        g_CtH[idx] = hs; g_CtL[idx] = ls;
    }
    if (y == 0 && t < 64) {
        float s = 0.f;
        for (int g = 0; g < 64; g++) s += sbq[g] * sWk[g][t];
        g_cb[al*64 + t] = s;
    }
}

// ---------------- fused attention ----------------
__global__ __launch_bounds__(256, 2) void attn_kernel(
    const float* __restrict__ X, const float* __restrict__ bt,
    float* __restrict__ out)
{
    extern __shared__ u32 sm[];
    u32* winH = sm;                    // [112][PW]; winL follows (+112*PW)
    u32* winL = winH + 112*PW;
    u32* ctH  = winL + 112*PW;         // [64][PW]; ctL follows — C^T, later wgt
    u32* ctL  = ctH + 64*PW;
    u32* wtH  = ctL + 64*PW;
    u32* wtL  = wtH + 64*PW;
    u32* uH   = wtL + 64*PW;           // U planes, later ctx
    u32* uL   = uH + 64*PW;
    float* sAttn = (float*)(uL + 64*PW);   // [64][PA]
    float* sFlag = sAttn + 64*PA;          // 112
    float* sBt   = sFlag + 112;            // 64
    float* scb   = sBt + 64;               // 64

    int bx = blockIdx.x;
    int st = bx & 31, b = (bx >> 5) & 3, al = bx >> 7;
    int a = al >> 2, l = al & 3;
    int s0 = st * 64;
    int t = threadIdx.x;
    int lane = t & 31;
    int gid = lane >> 2, tig = lane & 3;
    int w = t >> 5, mb = w & 3, h = w >> 2;
    int m0 = mb * 16;

    u32 bWinH = s2u(winH), bCtH = s2u(ctH), bWtH = s2u(wtH), bUH = s2u(uH);
    const u32 dWin = 112*PWB, dP = 64*PWB;   // H->L deltas

    // ---- window load: split planes + ballot flags ----
#pragma unroll
    for (int it = 0; it < 7; it++) {
        int q = t + it*256;
        int r = q >> 4, c4 = q & 15;
        int sg = s0 - KH + r;
        float4 v = make_float4(0.f, 0.f, 0.f, 0.f);
        if (sg >= 0 && sg < 2048)
            v = *(const float4*)&X[(((size_t)b*2048 + sg)*4 + a)*64 + c4*4];
        u32 h01, l01, h23, l23;
        splitp(v.x, v.y, h01, l01);
        splitp(v.z, v.w, h23, l23);
        winH[r*PW + c4*2] = h01; winH[r*PW + c4*2 + 1] = h23;
        winL[r*PW + c4*2] = l01; winL[r*PW + c4*2 + 1] = l23;
        bool nz = (v.x != 0.f) | (v.y != 0.f) | (v.z != 0.f) | (v.w != 0.f);
        u32 m = __ballot_sync(0xFFFFFFFFu, nz);
        if (lane == 0)  sFlag[r] = (m & 0xFFFFu) ? 1.f : 0.f;
        if (lane == 16) sFlag[r] = (m >> 16)     ? 1.f : 0.f;
    }
    const u32* gCtH = (const u32*)g_CtH + al*2048;
    const u32* gCtL = (const u32*)g_CtL + al*2048;
    const u32* gWtH = (const u32*)g_WtH + al*2048;
    const u32* gWtL = (const u32*)g_WtL + al*2048;
#pragma unroll
    for (int it = 0; it < 8; it++) {
        int q = t + it*256;
        int r = q >> 5, c = q & 31;
        ctH[r*PW + c] = gCtH[q]; ctL[r*PW + c] = gCtL[q];
        wtH[r*PW + c] = gWtH[q]; wtL[r*PW + c] = gWtL[q];
    }
    if (t < 64) {
        scb[t] = g_cb[al*64 + t];
        sBt[t] = bt[((7 + a)*5 + l)*64 + t];
    }
    __syncthreads();

    // ---- U = Xc*C + cb ----
    {
        float d[4][4] = {};
        u32 ah[4], alo[4], bh[2], bl[2];
#pragma unroll
        for (int ks = 0; ks < 4; ks++) {
            int kB = ks*32;
            u32 adA = bWinH + (KH + m0 + (lane & 15))*PWB + kB + ((lane >> 4) << 4);
            LDSM4(ah, adA); LDSM4(alo, adA + dWin);
#pragma unroll
            for (int nt = 0; nt < 4; nt++) {
                u32 adB = bCtH + (h*32 + nt*8 + (lane & 7))*PWB + kB + (((lane >> 3) & 1) << 4);
                LDSM2(bh, adB); LDSM2(bl, adB + dP);
                mma3(d[nt], ah, alo, bh, bl);
            }
        }
#pragma unroll
        for (int nt = 0; nt < 4; nt++) {
            int c0 = h*32 + nt*8 + tig*2;
            float cb0 = scb[c0], cb1 = scb[c0+1];
            u32 hi, lo;
            splitp(d[nt][0] + cb0, d[nt][1] + cb1, hi, lo);
            uH[(m0+gid)*PW + c0/2] = hi; uL[(m0+gid)*PW + c0/2] = lo;
            splitp(d[nt][2] + cb0, d[nt][3] + cb1, hi, lo);
            uH[(m0+gid+8)*PW + c0/2] = hi; uL[(m0+gid+8)*PW + c0/2] = lo;
        }
    }
    __syncthreads();

    // ---- scores: U x win rows m0+rel ----
    {
        int ntiles = (h == 0) ? 4 : 3;
        float d[4][4] = {};
        u32 ah[4], alo[4], bh[2], bl[2];
#pragma unroll
        for (int ks = 0; ks < 4; ks++) {
            int kB = ks*32;
            u32 adA = bUH + (m0 + (lane & 15))*PWB + kB + ((lane >> 4) << 4);
            LDSM4(ah, adA); LDSM4(alo, adA + dP);
            for (int nt = 0; nt < ntiles; nt++) {
                u32 adB = bWinH + (m0 + h*32 + nt*8 + (lane & 7))*PWB + kB + (((lane >> 3) & 1) << 4);
                LDSM2(bh, adB); LDSM2(bl, adB + dWin);
                mma3(d[nt], ah, alo, bh, bl);
            }
        }
        for (int nt = 0; nt < ntiles; nt++) {
            int c0 = h*32 + nt*8 + tig*2;
            sAttn[(m0+gid)*PA + c0]     = d[nt][0];
            sAttn[(m0+gid)*PA + c0+1]   = d[nt][1];
            sAttn[(m0+gid+8)*PA + c0]   = d[nt][2];
            sAttn[(m0+gid+8)*PA + c0+1] = d[nt][3];
        }
    }
    __syncthreads();

    // ---- softmax: 4 threads per query ----
    {
        int q = t >> 2, sub = t & 3;
        int srem = q & 15;
        float* row = &sAttn[q*PA];
        float m = -1e30f;
        for (int j = sub; j <= 40; j += 4) {
            float v = row[srem + j] * 0.125f;
            if (sFlag[q + j] == 0.f) v = -1e9f;
            row[srem + j] = v;
            m = fmaxf(m, v);
        }
        m = fmaxf(m, __shfl_xor_sync(0xFFFFFFFFu, m, 1));
        m = fmaxf(m, __shfl_xor_sync(0xFFFFFFFFu, m, 2));
        float ssum = 0.f;
        for (int j = sub; j <= 40; j += 4) {
            float e = __expf(row[srem + j] - m);
            row[srem + j] = e;
            ssum += e;
        }
        ssum += __shfl_xor_sync(0xFFFFFFFFu, ssum, 1);
        ssum += __shfl_xor_sync(0xFFFFFFFFu, ssum, 2);
        float inv = 1.f / ssum;
        __syncwarp();
        for (int rr = sub*16; rr < sub*16 + 16; rr += 2) {
            float w0 = (rr   >= srem && rr   <= srem + 40) ? row[rr]   * inv : 0.f;
            float w1 = (rr+1 >= srem && rr+1 <= srem + 40) ? row[rr+1] * inv : 0.f;
            u32 hi, lo;
            splitp(w0, w1, hi, lo);
            ctH[q*PW + rr/2] = hi; ctL[q*PW + rr/2] = lo;
        }
    }
    __syncthreads();

    // ---- ctx = wgt x win (B via ldmatrix.trans) ----
    {
        float d[4][4] = {};
        u32 ah[4], alo[4], bh[2], bl[2];
#pragma unroll
        for (int ks = 0; ks < 4; ks++) {
            int kB = ks*32;
            u32 adA = bCtH + (m0 + (lane & 15))*PWB + kB + ((lane >> 4) << 4);
            LDSM4(ah, adA); LDSM4(alo, adA + dP);
#pragma unroll
            for (int nt = 0; nt < 4; nt++) {
                u32 adB = bWinH + (m0 + ks*16 + (lane & 15))*PWB + (h*32 + nt*8)*2;
                LDSM2T(bh, adB); LDSM2T(bl, adB + dWin);
                mma3(d[nt], ah, alo, bh, bl);
            }
        }
        __syncthreads();   // U planes fully consumed; safe to overwrite
#pragma unroll
        for (int nt = 0; nt < 4; nt++) {
            int c0 = h*32 + nt*8 + tig*2;
            u32 hi, lo;
            splitp(d[nt][0], d[nt][1], hi, lo);
            uH[(m0+gid)*PW + c0/2] = hi; uL[(m0+gid)*PW + c0/2] = lo;
            splitp(d[nt][2], d[nt][3], hi, lo);
            uH[(m0+gid+8)*PW + c0/2] = hi; uL[(m0+gid+8)*PW + c0/2] = lo;
        }
    }
    __syncthreads();

    // ---- out = ctx x Wt^T + bt ----
    {
        float d[4][4] = {};
        u32 ah[4], alo[4], bh[2], bl[2];
#pragma unroll
        for (int ks = 0; ks < 4; ks++) {
            int kB = ks*32;
            u32 adA = bUH + (m0 + (lane & 15))*PWB + kB + ((lane >> 4) << 4);
            LDSM4(ah, adA); LDSM4(alo, adA + dP);
#pragma unroll
            for (int nt = 0; nt < 4; nt++) {
                u32 adB = bWtH + (h*32 + nt*8 + (lane & 7))*PWB + kB + (((lane >> 3) & 1) << 4);
                LDSM2(bh, adB); LDSM2(bl, adB + dP);
                mma3(d[nt], ah, alo, bh, bl);
            }
        }
#pragma unroll
        for (int nt = 0; nt < 4; nt++) {
            int c0 = h*32 + nt*8 + tig*2;
            int q0 = m0 + gid, q1 = m0 + gid + 8;
            size_t i0 = ((((size_t)b*2048 + s0 + q0)*4 + a)*4 + l)*64 + c0;
            size_t i1 = ((((size_t)b*2048 + s0 + q1)*4 + a)*4 + l)*64 + c0;
            *(float2*)&out[i0] = make_float2(d[nt][0] + sBt[c0], d[nt][1] + sBt[c0+1]);
            *(float2*)&out[i1] = make_float2(d[nt][2] + sBt[c0], d[nt][3] + sBt[c0+1]);
        }
    }
}

#define SMEM_BYTES ((112*PW*2 + 64*PW*6 + 64*PA + 112 + 128) * 4)

extern "C" void kernel_launch(void* const* d_in, const int* in_sizes, int n_in,
                              void* d_out, int out_size) {
    (void)in_sizes; (void)n_in; (void)out_size;
    const float* X  = (const float*)d_in[0];
    const float* Wq = (const float*)d_in[1];
    const float* bq = (const float*)d_in[2];
    const float* Wk = (const float*)d_in[3];
    const float* Wt = (const float*)d_in[5];
    const float* bt = (const float*)d_in[6];
    float* out = (float*)d_out;
    cudaFuncSetAttribute(attn_kernel, cudaFuncAttributeMaxDynamicSharedMemorySize, SMEM_BYTES);
    precompute_kernel<<<dim3(16,4), 256>>>(Wq, bq, Wk, Wt);
    attn_kernel<<<2048, 256, SMEM_BYTES>>>(X, bt, out);
}

// round 10
// speedup vs baseline: 3.1097x; 1.1476x over previous
#include <cuda_runtime.h>
#include <cuda_bf16.h>
#include <cstdint>
typedef unsigned short u16;
typedef uint32_t u32;

#define KH 20
#define PW 36            // plane pitch in u32
#define PWB 144          // plane pitch in bytes
#define PA 68            // f32 attn pitch

__device__ u16 g_CtH[16*4096], g_CtL[16*4096];   // [al][fo][fi]
__device__ u16 g_WtH[16*4096], g_WtL[16*4096];   // [al][g][f]
__device__ float g_cb[16*64];

__device__ __forceinline__ u32 bf2(float a, float b){
    u32 r; asm("cvt.rn.bf16x2.f32 %0, %1, %2;" : "=r"(r) : "f"(b), "f"(a)); return r;
}
__device__ __forceinline__ void splitp(float a, float b, u32& hi, u32& lo){
    hi = bf2(a, b);
    float ha = __uint_as_float(hi << 16);
    float hb = __uint_as_float(hi & 0xFFFF0000u);
    lo = bf2(a - ha, b - hb);
}
__device__ __forceinline__ void splits(float v, u16& hs, u16& ls){
    u32 hi, lo;
    splitp(v, 0.f, hi, lo);
    hs = (u16)(hi & 0xFFFFu); ls = (u16)(lo & 0xFFFFu);
}
__device__ __forceinline__ u32 s2u(const void* p){
    u32 a; asm("{ .reg .u64 t; cvta.to.shared.u64 t, %1; cvt.u32.u64 %0, t; }" : "=r"(a) : "l"(p));
    return a;
}
#define MMAB(d, a, b) asm volatile( \
  "mma.sync.aligned.m16n8k16.row.col.f32.bf16.bf16.f32 " \
  "{%0,%1,%2,%3},{%4,%5,%6,%7},{%8,%9},{%0,%1,%2,%3};" \
  : "+f"((d)[0]),"+f"((d)[1]),"+f"((d)[2]),"+f"((d)[3]) \
  : "r"((a)[0]),"r"((a)[1]),"r"((a)[2]),"r"((a)[3]),"r"((b)[0]),"r"((b)[1]))
__device__ __forceinline__ void mma3(float* d, const u32* ah, const u32* al,
                                     const u32* bh, const u32* bl){
    MMAB(d, ah, bh); MMAB(d, al, bh); MMAB(d, ah, bl);
}
#define LDSM4(r, ad) asm volatile("ldmatrix.sync.aligned.m8n8.x4.shared.b16 {%0,%1,%2,%3}, [%4];" \
    : "=r"((r)[0]),"=r"((r)[1]),"=r"((r)[2]),"=r"((r)[3]) : "r"(ad))
#define LDSM2(r, ad) asm volatile("ldmatrix.sync.aligned.m8n8.x2.shared.b16 {%0,%1}, [%2];" \
    : "=r"((r)[0]),"=r"((r)[1]) : "r"(ad))
#define LDSM4T(r, ad) asm volatile("ldmatrix.sync.aligned.m8n8.x4.trans.shared.b16 {%0,%1,%2,%3}, [%4];" \
    : "=r"((r)[0]),"=r"((r)[1]),"=r"((r)[2]),"=r"((r)[3]) : "r"(ad))

// ---------------- precompute: grid (16, 4) ----------------
__global__ __launch_bounds__(256) void precompute_kernel(
    const float* __restrict__ Wq, const float* __restrict__ bq,
    const float* __restrict__ Wk, const float* __restrict__ Wt)
{
    __shared__ float sWq[64][65], sWk[64][65], sbq[64];
    int al = blockIdx.x, y = blockIdx.y;
    int a = al >> 2, l = al & 3;
    size_t wb = ((size_t)(7 + a) * 5 + l) * 4096;
    size_t bb = ((size_t)(7 + a) * 5 + l) * 64;
    int t = threadIdx.x;
    for (int i = t; i < 4096; i += 256) {
        sWq[i >> 6][i & 63] = Wq[wb + i];
        sWk[i >> 6][i & 63] = Wk[wb + i];
    }
#pragma unroll
    for (int it = 0; it < 4; it++) {
        int i = y*1024 + it*256 + t;
        u16 hs, ls;
        splits(Wt[wb + i], hs, ls);
        g_WtH[al*4096 + i] = hs; g_WtL[al*4096 + i] = ls;
    }
    if (t < 64) sbq[t] = bq[bb + t];
    __syncthreads();
    int tf = t & 15, fr = t >> 4;
    int fi = y*16 + fr;
    float acc[4] = {};
    for (int g = 0; g < 64; g++) {
        float qv = sWq[g][fi];
#pragma unroll
        for (int j = 0; j < 4; j++) acc[j] += qv * sWk[g][tf*4 + j];
    }
#pragma unroll
    for (int j = 0; j < 4; j++) {
        u16 hs, ls;
        splits(acc[j], hs, ls);
        int idx = al*4096 + (tf*4+j)*64 + fi;
        g_CtH[idx] = hs; g_CtL[idx] = ls;
    }
    if (y == 0 && t < 64) {
        float s = 0.f;
        for (int g = 0; g < 64; g++) s += sbq[g] * sWk[g][t];
        g_cb[al*64 + t] = s;
    }
}

// ---------------- fused attention ----------------
__global__ __launch_bounds__(256, 2) void attn_kernel(
    const float* __restrict__ X, const float* __restrict__ bt,
    float* __restrict__ out)
{
    extern __shared__ u32 sm[];
    u32* winH = sm;
    u32* winL = winH + 112*PW;
    u32* ctH  = winL + 112*PW;         // C^T planes, later wgt
    u32* ctL  = ctH + 64*PW;
    u32* wtH  = ctL + 64*PW;
    u32* wtL  = wtH + 64*PW;
    u32* uH   = wtL + 64*PW;           // U planes, later ctx
    u32* uL   = uH + 64*PW;
    float* sAttn = (float*)(uL + 64*PW);
    float* sFlag = sAttn + 64*PA;
    float* sBt   = sFlag + 112;
    float* scb   = sBt + 64;

    int bx = blockIdx.x;
    int st = bx & 31, b = (bx >> 5) & 3, al = bx >> 7;
    int a = al >> 2, l = al & 3;
    int s0 = st * 64;
    int t = threadIdx.x;
    int lane = t & 31;
    int gid = lane >> 2, tig = lane & 3;
    int w = t >> 5, mb = w & 3, h = w >> 2;
    int m0 = mb * 16;

    u32 bWinH = s2u(winH), bCtH = s2u(ctH), bWtH = s2u(wtH), bUH = s2u(uH);
    const u32 dWin = 112*PWB, dP = 64*PWB;

    // lane-mapped offsets
    const u32 offA  = (lane & 15)*PWB + ((lane >> 4) << 4);              // A x4
    const u32 offBP = ((lane & 7) + ((lane & 16) >> 1))*PWB + ((lane & 8) << 1); // B pair x4
    const u32 offBS = (lane & 7)*PWB + ((lane & 8) << 1);                // B single x2
    const u32 offBT = (lane & 15)*PWB + (((lane & 16) >> 1) << 1);       // B trans pair x4 (col +8n*2B)

    // ---- window load ----
#pragma unroll
    for (int it = 0; it < 7; it++) {
        int q = t + it*256;
        int r = q >> 4, c4 = q & 15;
        int sg = s0 - KH + r;
        float4 v = make_float4(0.f, 0.f, 0.f, 0.f);
        if (sg >= 0 && sg < 2048)
            v = *(const float4*)&X[(((size_t)b*2048 + sg)*4 + a)*64 + c4*4];
        u32 h01, l01, h23, l23;
        splitp(v.x, v.y, h01, l01);
        splitp(v.z, v.w, h23, l23);
        winH[r*PW + c4*2] = h01; winH[r*PW + c4*2 + 1] = h23;
        winL[r*PW + c4*2] = l01; winL[r*PW + c4*2 + 1] = l23;
        bool nz = (v.x != 0.f) | (v.y != 0.f) | (v.z != 0.f) | (v.w != 0.f);
        u32 m = __ballot_sync(0xFFFFFFFFu, nz);
        if (lane == 0)  sFlag[r] = (m & 0xFFFFu) ? 1.f : 0.f;
        if (lane == 16) sFlag[r] = (m >> 16)     ? 1.f : 0.f;
    }
    const u32* gCtH = (const u32*)g_CtH + al*2048;
    const u32* gCtL = (const u32*)g_CtL + al*2048;
    const u32* gWtH = (const u32*)g_WtH + al*2048;
    const u32* gWtL = (const u32*)g_WtL + al*2048;
#pragma unroll
    for (int it = 0; it < 8; it++) {
        int q = t + it*256;
        int r = q >> 5, c = q & 31;
        ctH[r*PW + c] = gCtH[q]; ctL[r*PW + c] = gCtL[q];
        wtH[r*PW + c] = gWtH[q]; wtL[r*PW + c] = gWtL[q];
    }
    if (t < 64) {
        scb[t] = g_cb[al*64 + t];
        sBt[t] = bt[((7 + a)*5 + l)*64 + t];
    }
    __syncthreads();

    // ---- U = Xc*C + cb ----
    {
        float d[4][4] = {};
        u32 aB0[8], aB1[8], bhp[2][4], blp[2][4];
        u32 adA = bWinH + (KH + m0)*PWB + offA;
        LDSM4(aB0, adA); LDSM4(aB0+4, adA + dWin);
#pragma unroll
        for (int ks = 0; ks < 4; ks++) {
            int kB = ks*32;
            u32 adB0 = bCtH + (h*32)*PWB + offBP + kB;
            u32 adB1 = adB0 + 16*PWB;
            LDSM4(bhp[0], adB0); LDSM4(blp[0], adB0 + dP);
            LDSM4(bhp[1], adB1); LDSM4(blp[1], adB1 + dP);
            u32* cur = (ks & 1) ? aB1 : aB0;
            if (ks < 3) {
                u32* nxt = (ks & 1) ? aB0 : aB1;
                u32 adN = adA + kB + 32;
                LDSM4(nxt, adN); LDSM4(nxt+4, adN + dWin);
            }
#pragma unroll
            for (int p = 0; p < 2; p++) {
                mma3(d[p*2],   cur, cur+4, bhp[p],   blp[p]);
                mma3(d[p*2+1], cur, cur+4, bhp[p]+2, blp[p]+2);
            }
        }
#pragma unroll
        for (int nt = 0; nt < 4; nt++) {
            int c0 = h*32 + nt*8 + tig*2;
            float cb0 = scb[c0], cb1 = scb[c0+1];
            u32 hi, lo;
            splitp(d[nt][0] + cb0, d[nt][1] + cb1, hi, lo);
            uH[(m0+gid)*PW + c0/2] = hi; uL[(m0+gid)*PW + c0/2] = lo;
            splitp(d[nt][2] + cb0, d[nt][3] + cb1, hi, lo);
            uH[(m0+gid+8)*PW + c0/2] = hi; uL[(m0+gid+8)*PW + c0/2] = lo;
        }
    }
    __syncthreads();

    // ---- scores: U x win rows m0+rel ----
    {
        float d[4][4] = {};
        u32 aB0[8], aB1[8], bhp[2][4], blp[2][4];
        u32 adA = bUH + m0*PWB + offA;
        LDSM4(aB0, adA); LDSM4(aB0+4, adA + dP);
#pragma unroll
        for (int ks = 0; ks < 4; ks++) {
            int kB = ks*32;
            u32 adB0 = bWinH + (m0 + h*32)*PWB + offBP + kB;
            LDSM4(bhp[0], adB0); LDSM4(blp[0], adB0 + dWin);
            if (h == 0) {
                u32 adB1 = adB0 + 16*PWB;
                LDSM4(bhp[1], adB1); LDSM4(blp[1], adB1 + dWin);
            } else {
                u32 adB1 = bWinH + (m0 + 48)*PWB + offBS + kB;
                LDSM2(bhp[1], adB1); LDSM2(blp[1], adB1 + dWin);
            }
            u32* cur = (ks & 1) ? aB1 : aB0;
            if (ks < 3) {
                u32* nxt = (ks & 1) ? aB0 : aB1;
                u32 adN = adA + kB + 32;
                LDSM4(nxt, adN); LDSM4(nxt+4, adN + dP);
            }
            mma3(d[0], cur, cur+4, bhp[0],   blp[0]);
            mma3(d[1], cur, cur+4, bhp[0]+2, blp[0]+2);
            mma3(d[2], cur, cur+4, bhp[1],   blp[1]);
            if (h == 0) mma3(d[3], cur, cur+4, bhp[1]+2, blp[1]+2);
        }
        int ntiles = (h == 0) ? 4 : 3;
        for (int nt = 0; nt < ntiles; nt++) {
            int c0 = h*32 + nt*8 + tig*2;
            sAttn[(m0+gid)*PA + c0]     = d[nt][0];
            sAttn[(m0+gid)*PA + c0+1]   = d[nt][1];
            sAttn[(m0+gid+8)*PA + c0]   = d[nt][2];
            sAttn[(m0+gid+8)*PA + c0+1] = d[nt][3];
        }
    }
    __syncthreads();

    // ---- softmax: 4 threads per query ----
    {
        int q = t >> 2, sub = t & 3;
        int srem = q & 15;
        float* row = &sAttn[q*PA];
        float m = -1e30f;
        for (int j = sub; j <= 40; j += 4) {
            float v = row[srem + j] * 0.125f;
            if (sFlag[q + j] == 0.f) v = -1e9f;
            row[srem + j] = v;
            m = fmaxf(m, v);
        }
        m = fmaxf(m, __shfl_xor_sync(0xFFFFFFFFu, m, 1));
        m = fmaxf(m, __shfl_xor_sync(0xFFFFFFFFu, m, 2));
        float ssum = 0.f;
        for (int j = sub; j <= 40; j += 4) {
            float e = __expf(row[srem + j] - m);
            row[srem + j] = e;
            ssum += e;
        }
        ssum += __shfl_xor_sync(0xFFFFFFFFu, ssum, 1);
        ssum += __shfl_xor_sync(0xFFFFFFFFu, ssum, 2);
        float inv = 1.f / ssum;
        __syncwarp();
        for (int rr = sub*16; rr < sub*16 + 16; rr += 2) {
            float w0 = (rr   >= srem && rr   <= srem + 40) ? row[rr]   * inv : 0.f;
            float w1 = (rr+1 >= srem && rr+1 <= srem + 40) ? row[rr+1] * inv : 0.f;
            u32 hi, lo;
            splitp(w0, w1, hi, lo);
            ctH[q*PW + rr/2] = hi; ctL[q*PW + rr/2] = lo;
        }
    }
    __syncthreads();

    // ---- ctx = wgt x win (B via ldmatrix.x4.trans pairs) ----
    {
        float d[4][4] = {};
        u32 aB0[8], aB1[8], bhp[2][4], blp[2][4];
        u32 adA = bCtH + m0*PWB + offA;
        LDSM4(aB0, adA); LDSM4(aB0+4, adA + dP);
#pragma unroll
        for (int ks = 0; ks < 4; ks++) {
            int kB = ks*32;
            u32 adB0 = bWinH + (m0 + ks*16)*PWB + offBT + (h*32)*2;
            u32 adB1 = adB0 + 32;  // +16 n columns * 2B
            LDSM4T(bhp[0], adB0); LDSM4T(blp[0], adB0 + dWin);
            LDSM4T(bhp[1], adB1); LDSM4T(blp[1], adB1 + dWin);
            u32* cur = (ks & 1) ? aB1 : aB0;
            if (ks < 3) {
                u32* nxt = (ks & 1) ? aB0 : aB1;
                u32 adN = adA + kB + 32;
                LDSM4(nxt, adN); LDSM4(nxt+4, adN + dP);
            }
#pragma unroll
            for (int p = 0; p < 2; p++) {
                mma3(d[p*2],   cur, cur+4, bhp[p],   blp[p]);
                mma3(d[p*2+1], cur, cur+4, bhp[p]+2, blp[p]+2);
            }
        }
        __syncthreads();
#pragma unroll
        for (int nt = 0; nt < 4; nt++) {
            int c0 = h*32 + nt*8 + tig*2;
            u32 hi, lo;
            splitp(d[nt][0], d[nt][1], hi, lo);
            uH[(m0+gid)*PW + c0/2] = hi; uL[(m0+gid)*PW + c0/2] = lo;
            splitp(d[nt][2], d[nt][3], hi, lo);
            uH[(m0+gid+8)*PW + c0/2] = hi; uL[(m0+gid+8)*PW + c0/2] = lo;
        }
    }
    __syncthreads();

    // ---- out = ctx x Wt^T + bt ----
    {
        float d[4][4] = {};
        u32 aB0[8], aB1[8], bhp[2][4], blp[2][4];
        u32 adA = bUH + m0*PWB + offA;
        LDSM4(aB0, adA); LDSM4(aB0+4, adA + dP);
#pragma unroll
        for (int ks = 0; ks < 4; ks++) {
            int kB = ks*32;
            u32 adB0 = bWtH + (h*32)*PWB + offBP + kB;
            u32 adB1 = adB0 + 16*PWB;
            LDSM4(bhp[0], adB0); LDSM4(blp[0], adB0 + dP);
            LDSM4(bhp[1], adB1); LDSM4(blp[1], adB1 + dP);
            u32* cur = (ks & 1) ? aB1 : aB0;
            if (ks < 3) {
                u32* nxt = (ks & 1) ? aB0 : aB1;
                u32 adN = adA + kB + 32;
                LDSM4(nxt, adN); LDSM4(nxt+4, adN + dP);
            }
#pragma unroll
            for (int p = 0; p < 2; p++) {
                mma3(d[p*2],   cur, cur+4, bhp[p],   blp[p]);
                mma3(d[p*2+1], cur, cur+4, bhp[p]+2, blp[p]+2);
            }
        }
#pragma unroll
        for (int nt = 0; nt < 4; nt++) {
            int c0 = h*32 + nt*8 + tig*2;
            int q0 = m0 + gid, q1 = m0 + gid + 8;
            size_t i0 = ((((size_t)b*2048 + s0 + q0)*4 + a)*4 + l)*64 + c0;
            size_t i1 = ((((size_t)b*2048 + s0 + q1)*4 + a)*4 + l)*64 + c0;
            *(float2*)&out[i0] = make_float2(d[nt][0] + sBt[c0], d[nt][1] + sBt[c0+1]);
            *(float2*)&out[i1] = make_float2(d[nt][2] + sBt[c0], d[nt][3] + sBt[c0+1]);
        }
    }
}

#define SMEM_BYTES ((112*PW*2 + 64*PW*6 + 64*PA + 112 + 128) * 4)

extern "C" void kernel_launch(void* const* d_in, const int* in_sizes, int n_in,
                              void* d_out, int out_size) {
    (void)in_sizes; (void)n_in; (void)out_size;
    const float* X  = (const float*)d_in[0];
    const float* Wq = (const float*)d_in[1];
    const float* bq = (const float*)d_in[2];
    const float* Wk = (const float*)d_in[3];
    const float* Wt = (const float*)d_in[5];
    const float* bt = (const float*)d_in[6];
    float* out = (float*)d_out;
    cudaFuncSetAttribute(attn_kernel, cudaFuncAttributeMaxDynamicSharedMemorySize, SMEM_BYTES);
    precompute_kernel<<<dim3(16,4), 256>>>(Wq, bq, Wk, Wt);
    attn_kernel<<<2048, 256, SMEM_BYTES>>>(X, bt, out);
}